// round 8
// baseline (speedup 1.0000x reference)
#include <cuda_runtime.h>
#include <cuda_bf16.h>
#include <cstdint>

// B=4, N=256, OBS=40, ACT=8, HEAD=8, DIM=32, T=256
// Algebra: nh/hid independent of broadcast index -> only column sums S_n,S_h;
// final gather at tgt -> ah needed at 4 rows only.
// GEMMs: bf16 2-term split (3 mma per product, fp32 accum), warp-autonomous
// 32-thread blocks, 32x32 C tile per warp, K=256 serial, cp.async k32 chunks,
// NO block barriers anywhere in the GEMM.

__device__ __align__(256) __nv_bfloat16 g_E1h[1024*256], g_E1l[1024*256];
__device__ __align__(256) __nv_bfloat16 g_We2Th[256*256], g_We2Tl[256*256];
__device__ __align__(256) __nv_bfloat16 g_WnTh[256*256],  g_WnTl[256*256];
__device__ __align__(256) __nv_bfloat16 g_WhTh[256*256],  g_WhTl[256*256];
__device__ __align__(256) __nv_bfloat16 g_adjh[256*256],  g_adjl[256*256];
__device__ __align__(256) __nv_bfloat16 g_E2fTh[4*256*256], g_E2fTl[4*256*256];
__device__ __align__(256) __nv_bfloat16 g_NEfh[1024*256], g_NEfl[1024*256];
__device__ float g_Sn[1024], g_Sh[1024], g_AH[1024];

__device__ __forceinline__ void bsplit(float v, __nv_bfloat16* ph, __nv_bfloat16* pl) {
    __nv_bfloat16 h = __float2bfloat16(v);
    *ph = h;
    *pl = __float2bfloat16(v - __bfloat162float(h));
}
__device__ __forceinline__ uint32_t packsplit(float v0, float v1, uint32_t* lo) {
    __nv_bfloat16 h0 = __float2bfloat16(v0), h1 = __float2bfloat16(v1);
    __nv_bfloat16 l0 = __float2bfloat16(v0 - __bfloat162float(h0));
    __nv_bfloat16 l1 = __float2bfloat16(v1 - __bfloat162float(h1));
    *lo = (uint32_t)*(uint16_t*)&l0 | ((uint32_t)*(uint16_t*)&l1 << 16);
    return (uint32_t)*(uint16_t*)&h0 | ((uint32_t)*(uint16_t*)&h1 << 16);
}
__device__ __forceinline__ void cp16(uint32_t dst, const void* src) {
    asm volatile("cp.async.ca.shared.global [%0], [%1], 16;\n" :: "r"(dst), "l"(src));
}
__device__ __forceinline__ void ldm_x4(uint32_t* r, uint32_t addr) {
    asm volatile("ldmatrix.sync.aligned.m8n8.x4.shared.b16 {%0,%1,%2,%3}, [%4];"
                 : "=r"(r[0]), "=r"(r[1]), "=r"(r[2]), "=r"(r[3]) : "r"(addr));
}
__device__ __forceinline__ void mma_bf16(float* d, const uint32_t* a, uint32_t b0, uint32_t b1) {
    asm volatile("mma.sync.aligned.m16n8k16.row.col.f32.bf16.bf16.f32 "
                 "{%0,%1,%2,%3}, {%4,%5,%6,%7}, {%8,%9}, {%0,%1,%2,%3};"
                 : "+f"(d[0]), "+f"(d[1]), "+f"(d[2]), "+f"(d[3])
                 : "r"(a[0]), "r"(a[1]), "r"(a[2]), "r"(a[3]), "r"(b0), "r"(b1));
}

// ---------------------------------------------------------------------------
__global__ void k_embed1(const float* __restrict__ x, const float* __restrict__ We1,
                         const float* __restrict__ be1) {
    __shared__ float xs[4][40];
    int r0 = blockIdx.x * 4;
    int tid = threadIdx.x;
    if (blockIdx.x == 0) {
#pragma unroll
        for (int i = 0; i < 4; i++) {
            g_Sn[i * 256 + tid] = 0.f;
            g_Sh[i * 256 + tid] = 0.f;
            g_AH[i * 256 + tid] = 0.f;
        }
    }
    if (tid < 160) {
        int rr = tid / 40, k = tid % 40;
        int row = r0 + rr;
        int b = row >> 8, i = row & 255;
        xs[rr][k] = x[b * 257 * 40 + i * 40 + k];
    }
    __syncthreads();
    float bias = be1[tid];
    float acc[4] = {bias, bias, bias, bias};
#pragma unroll
    for (int k = 0; k < 40; k++) {
        float w = We1[k * 256 + tid];
#pragma unroll
        for (int rr = 0; rr < 4; rr++) acc[rr] += xs[rr][k] * w;
    }
#pragma unroll
    for (int rr = 0; rr < 4; rr++) {
        float v = fmaxf(acc[rr], 0.f);
        size_t o = (size_t)(r0 + rr) * 256 + tid;
        bsplit(v, &g_E1h[o], &g_E1l[o]);
    }
}

// ---------------------------------------------------------------------------
__global__ void k_convW(const float* __restrict__ We2, const float* __restrict__ Wn,
                        const float* __restrict__ Wh, const float* __restrict__ adj) {
    __shared__ float ts[32][33];
    int z = blockIdx.z;
    int tx = threadIdx.x, ty = threadIdx.y;
    int n0 = blockIdx.x * 32, k0 = blockIdx.y * 32;
    const float* in = (z == 0) ? We2 : (z == 1) ? Wn : (z == 2) ? Wh : adj;
    __nv_bfloat16* oh = (z == 0) ? g_We2Th : (z == 1) ? g_WnTh : (z == 2) ? g_WhTh : g_adjh;
    __nv_bfloat16* ol = (z == 0) ? g_We2Tl : (z == 1) ? g_WnTl : (z == 2) ? g_WhTl : g_adjl;
    if (z < 3) {
        for (int r = ty; r < 32; r += 8)
            ts[r][tx] = in[(size_t)(k0 + r) * 256 + n0 + tx];
        __syncthreads();
        for (int r = ty; r < 32; r += 8) {
            float v = ts[tx][r];
            size_t o = (size_t)(n0 + r) * 256 + k0 + tx;
            bsplit(v, &oh[o], &ol[o]);
        }
    } else {
        for (int r = ty; r < 32; r += 8) {
            size_t o = (size_t)(k0 + r) * 256 + n0 + tx;
            bsplit(in[o], &oh[o], &ol[o]);
        }
    }
}

// ---------------------------------------------------------------------------
// Warp-autonomous GEMM. MODE 0: E2->E2fT; MODE 1: NE->NEf (z=batch);
// MODE 2: colsum relu(NEf@W+bias) -> S (which/bias from args).
#define ROWB 80
#define ARRB (32 * ROWB)
#define STGB (4 * ARRB)

template <int MODE>
__global__ void __launch_bounds__(32) k_wg(const float* __restrict__ bias, int which) {
    __shared__ __align__(16) __nv_bfloat16 sm[2 * 4 * 32 * 40];
    int lane = threadIdx.x;
    int row0 = blockIdx.y * 32, col0 = blockIdx.x * 32;

    const __nv_bfloat16 *pAh, *pAl, *pBh, *pBl;
    size_t bExtra = 0;
    if (MODE == 0) { pAh = g_E1h;  pAl = g_E1l;  pBh = g_We2Th; pBl = g_We2Tl; }
    if (MODE == 1) { pAh = g_adjh; pAl = g_adjl; pBh = g_E2fTh; pBl = g_E2fTl;
                     bExtra = (size_t)blockIdx.z * 65536; }
    if (MODE == 2) { pAh = g_NEfh; pAl = g_NEfl;
                     pBh = which ? g_WhTh : g_WnTh;
                     pBl = which ? g_WhTl : g_WnTl; }

    const __nv_bfloat16* src[4] = {
        pAh + (size_t)(row0 + lane) * 256,
        pAl + (size_t)(row0 + lane) * 256,
        pBh + bExtra + (size_t)(col0 + lane) * 256,
        pBl + bExtra + (size_t)(col0 + lane) * 256 };
    uint32_t sbase = (uint32_t)__cvta_generic_to_shared(&sm[0]);

#define LOAD_CHUNK(c, st)                                                      \
    {                                                                          \
        _Pragma("unroll")                                                      \
        for (int a = 0; a < 4; a++) {                                          \
            uint32_t d = sbase + (st) * STGB + a * ARRB + lane * ROWB;         \
            const __nv_bfloat16* s = src[a] + (c) * 32;                        \
            cp16(d, s); cp16(d + 16, s + 8);                                   \
            cp16(d + 32, s + 16); cp16(d + 48, s + 24);                        \
        }                                                                      \
        asm volatile("cp.async.commit_group;\n" ::);                           \
    }

    LOAD_CHUNK(0, 0)

    int aRow = lane & 15;
    int aCol = (lane >> 4) << 3;
    int bRow = ((lane >> 4) << 3) + (lane & 7);
    int bCol = lane & 8;

    float acc[2][4][4] = {};
    for (int c = 0; c < 8; c++) {
        if (c < 7) {
            LOAD_CHUNK(c + 1, (c + 1) & 1)
            asm volatile("cp.async.wait_group 1;\n" ::);
        } else {
            asm volatile("cp.async.wait_group 0;\n" ::);
        }
        __syncwarp();
        uint32_t stB = sbase + (c & 1) * STGB;
#pragma unroll
        for (int ki = 0; ki < 2; ki++) {
            uint32_t ah[2][4], al[2][4], bh[2][4], bl[2][4];
#pragma unroll
            for (int mi = 0; mi < 2; mi++) {
                uint32_t off = (uint32_t)((mi * 16 + aRow) * ROWB + (ki * 16 + aCol) * 2);
                ldm_x4(ah[mi], stB + off);
                ldm_x4(al[mi], stB + ARRB + off);
            }
#pragma unroll
            for (int ti = 0; ti < 2; ti++) {
                uint32_t off = (uint32_t)((ti * 16 + bRow) * ROWB + (ki * 16 + bCol) * 2);
                ldm_x4(bh[ti], stB + 2 * ARRB + off);
                ldm_x4(bl[ti], stB + 3 * ARRB + off);
            }
#pragma unroll
            for (int mi = 0; mi < 2; mi++)
#pragma unroll
                for (int ni = 0; ni < 4; ni++) {
                    const uint32_t* BH = &bh[ni >> 1][(ni & 1) * 2];
                    const uint32_t* BL = &bl[ni >> 1][(ni & 1) * 2];
                    float* d = acc[mi][ni];
                    mma_bf16(d, ah[mi], BH[0], BH[1]);
                    mma_bf16(d, ah[mi], BL[0], BL[1]);
                    mma_bf16(d, al[mi], BH[0], BH[1]);
                }
        }
    }
#undef LOAD_CHUNK

    float (*red)[33] = reinterpret_cast<float(*)[33]>(&sm[0]);
#pragma unroll
    for (int mi = 0; mi < 2; mi++)
#pragma unroll
        for (int ni = 0; ni < 4; ni++)
#pragma unroll
            for (int r = 0; r < 4; r++)
                red[mi * 16 + (lane >> 2) + ((r >> 1) << 3)]
                   [ni * 8 + (lane & 3) * 2 + (r & 1)] = acc[mi][ni][r];
    __syncwarp();

    if (MODE == 0) {
        int b = row0 >> 8, i0 = row0 & 255;
        float bv = bias[col0 + lane];
        uint32_t wh[16], wl[16];
#pragma unroll
        for (int p = 0; p < 16; p++) {
            float v0 = fmaxf(red[2 * p][lane] + bv, 0.f);
            float v1 = fmaxf(red[2 * p + 1][lane] + bv, 0.f);
            wh[p] = packsplit(v0, v1, &wl[p]);
        }
        size_t o = (size_t)b * 65536 + (size_t)(col0 + lane) * 256 + i0;
        uint4* gh = (uint4*)(g_E2fTh + o);
        uint4* gl = (uint4*)(g_E2fTl + o);
#pragma unroll
        for (int q = 0; q < 4; q++) {
            gh[q] = make_uint4(wh[4*q], wh[4*q+1], wh[4*q+2], wh[4*q+3]);
            gl[q] = make_uint4(wl[4*q], wl[4*q+1], wl[4*q+2], wl[4*q+3]);
        }
    }
    if (MODE == 1) {
        uint32_t wh[16], wl[16];
#pragma unroll
        for (int p = 0; p < 16; p++)
            wh[p] = packsplit(red[lane][2 * p], red[lane][2 * p + 1], &wl[p]);
        size_t o = (size_t)(blockIdx.z * 256 + row0 + lane) * 256 + col0;
        uint4* gh = (uint4*)(g_NEfh + o);
        uint4* gl = (uint4*)(g_NEfl + o);
#pragma unroll
        for (int q = 0; q < 4; q++) {
            gh[q] = make_uint4(wh[4*q], wh[4*q+1], wh[4*q+2], wh[4*q+3]);
            gl[q] = make_uint4(wl[4*q], wl[4*q+1], wl[4*q+2], wl[4*q+3]);
        }
    }
    if (MODE == 2) {
        float bv = bias[col0 + lane];
        float s = 0.f;
#pragma unroll
        for (int r = 0; r < 32; r++) s += fmaxf(red[r][lane] + bv, 0.f);
        float* S = which ? g_Sh : g_Sn;
        atomicAdd(&S[(row0 >> 8) * 256 + col0 + lane], s);
    }
}

// ---------------------------------------------------------------------------
__global__ void k_ah(const float* __restrict__ x, const float* __restrict__ Wl) {
    __shared__ float vs[64];
    int b = blockIdx.x >> 2, kseg = blockIdx.x & 3;
    int t = threadIdx.x;
    int tgt = (int)x[b * 257 * 40 + 256 * 40];
    if (t < 64) {
        size_t o = (size_t)b * 65536 + (size_t)(kseg * 64 + t) * 256 + tgt;
        vs[t] = __bfloat162float(g_E2fTh[o]) + __bfloat162float(g_E2fTl[o]);
    }
    __syncthreads();
    float acc = 0.f;
#pragma unroll 8
    for (int k = 0; k < 64; k++)
        acc += vs[k] * Wl[(kseg * 64 + k) * 256 + t];
    atomicAdd(&g_AH[b * 256 + t], acc);
}

// ---------------------------------------------------------------------------
__global__ void k_final(const float* __restrict__ bl, const float* __restrict__ Wa,
                        const float* __restrict__ ba, float* __restrict__ out) {
    __shared__ float od[32];
    int b = blockIdx.x, tid = threadIdx.x;
    int h = tid >> 5, d = tid & 31;
    int t = d * 8 + h;
    float ahv = fmaxf(g_AH[b * 256 + t] + bl[t], 0.f);
    float logit = ahv * g_Sn[b * 256 + t];
    float m = logit;
#pragma unroll
    for (int o = 16; o > 0; o >>= 1) m = fmaxf(m, __shfl_xor_sync(0xffffffffu, m, o));
    float e = expf(logit - m);
    float ssum = e;
#pragma unroll
    for (int o = 16; o > 0; o >>= 1) ssum += __shfl_xor_sync(0xffffffffu, ssum, o);
    float val = (e / ssum) * g_Sh[b * 256 + t] * 0.125f;
    if (tid < 32) od[tid] = 0.f;
    __syncthreads();
    atomicAdd(&od[d], val);
    __syncthreads();
    if (tid < 8) {
        float acc = ba[tid];
#pragma unroll
        for (int dd = 0; dd < 32; dd++) acc += od[dd] * Wa[dd * 8 + tid];
        out[b * 8 + tid] = acc;
    }
    (void)h;
}

// ---------------------------------------------------------------------------
extern "C" void kernel_launch(void* const* d_in, const int* in_sizes, int n_in,
                              void* d_out, int out_size) {
    const float* x   = (const float*)d_in[0];
    const float* adj = (const float*)d_in[1];
    const float* We1 = (const float*)d_in[2];
    const float* be1 = (const float*)d_in[3];
    const float* We2 = (const float*)d_in[4];
    const float* be2 = (const float*)d_in[5];
    const float* Wl  = (const float*)d_in[6];
    const float* bl  = (const float*)d_in[7];
    const float* Wn  = (const float*)d_in[8];
    const float* bn  = (const float*)d_in[9];
    const float* Wh  = (const float*)d_in[10];
    const float* bh  = (const float*)d_in[11];
    const float* Wa  = (const float*)d_in[12];
    const float* ba  = (const float*)d_in[13];
    float* out = (float*)d_out;

    k_embed1<<<256, 256>>>(x, We1, be1);
    k_convW<<<dim3(8, 8, 4), dim3(32, 8)>>>(We2, Wn, Wh, adj);
    k_wg<0><<<dim3(8, 32, 1), 32>>>(be2, 0);
    k_wg<1><<<dim3(8, 8, 4), 32>>>(nullptr, 0);
    k_wg<2><<<dim3(8, 32, 1), 32>>>(bn, 0);
    k_wg<2><<<dim3(8, 32, 1), 32>>>(bh, 1);
    k_ah<<<16, 256>>>(x, Wl);
    k_final<<<4, 256>>>(bl, Wa, ba, out);

    (void)in_sizes; (void)n_in; (void)out_size;
}

// round 9
// speedup vs baseline: 1.2243x; 1.2243x over previous
#include <cuda_runtime.h>

// B=4, N=256, OBS=40, ACT=8, HEAD=8, DIM=32, T=256
// Algebra: nh/hid independent of broadcast index -> only column sums S_n,S_h (B,T);
// final gather at tgt -> ah needed at 4 rows only.
// Split-K=2 (atomic-free): producers write two partial buffers; consumers add at load.
// GEMMs: BM=64 BN=32 BK=16, 128 threads, 4x4 microtile (16 FFMA / 2 LDS),
// register-prefetch double-buffered smem. Grids 256 blocks each.

__device__ float g_E1[1024 * 256];
__device__ float g_E2[2 * 1024 * 256];   // [ksplit][row][col] partials of E1@We2
__device__ float g_NE[2 * 1024 * 256];   // [ksplit][b*256+i][col] partials of adj@relu_E2
__device__ float g_Sn[1024];
__device__ float g_Sh[1024];
__device__ float g_AH[1024];

#define E2_HALF (1024 * 256)

// ---------------------------------------------------------------------------
// K1: E1 = relu(obs @ We1 + be1); block 0 also zeroes the accumulators.
__global__ void k_embed1(const float* __restrict__ x, const float* __restrict__ We1,
                         const float* __restrict__ be1) {
    __shared__ float xs[4][40];
    int r0 = blockIdx.x * 4;
    int tid = threadIdx.x;
    if (blockIdx.x == 0) {
#pragma unroll
        for (int i = 0; i < 4; i++) {
            g_Sn[i * 256 + tid] = 0.f;
            g_Sh[i * 256 + tid] = 0.f;
            g_AH[i * 256 + tid] = 0.f;
        }
    }
    if (tid < 160) {
        int rr = tid / 40, k = tid % 40;
        int row = r0 + rr;
        int b = row >> 8, i = row & 255;
        xs[rr][k] = x[b * 257 * 40 + i * 40 + k];
    }
    __syncthreads();
    float bias = be1[tid];
    float acc[4] = {bias, bias, bias, bias};
#pragma unroll
    for (int k = 0; k < 40; k++) {
        float w = We1[k * 256 + tid];
#pragma unroll
        for (int rr = 0; rr < 4; rr++) acc[rr] += xs[rr][k] * w;
    }
#pragma unroll
    for (int rr = 0; rr < 4; rr++)
        g_E1[(r0 + rr) * 256 + tid] = fmaxf(acc[rr], 0.f);
}

// ---------------------------------------------------------------------------
// Tiling: BM=64 BN=32 BK=16, 128 threads.
// A loader: arow=tid>>1 (0..63), akq=tid&1 -> float4 at k = akq*4 and 8+akq*4,
//           stored transposed into As[k][m] (pad 68).
// B loader: brow=tid>>3 (0..15), bq=tid&7 -> float4 at n = bq*4 into Bs[k][n].
// Compute:  tx=tid&7 (cols tx*4), ty=tid>>3 (0..15, rows ty*4..ty*4+3), 4x4 acc.

#define MT_COMPUTE(As_, Bs_)                                                   \
    _Pragma("unroll")                                                          \
    for (int kk = 0; kk < 16; kk++) {                                          \
        float4 av = *(const float4*)&As_[kk][ty * 4];                          \
        float4 bv = *(const float4*)&Bs_[kk][tx * 4];                          \
        acc[0][0] += av.x * bv.x; acc[0][1] += av.x * bv.y;                    \
        acc[0][2] += av.x * bv.z; acc[0][3] += av.x * bv.w;                    \
        acc[1][0] += av.y * bv.x; acc[1][1] += av.y * bv.y;                    \
        acc[1][2] += av.y * bv.z; acc[1][3] += av.y * bv.w;                    \
        acc[2][0] += av.z * bv.x; acc[2][1] += av.z * bv.y;                    \
        acc[2][2] += av.z * bv.z; acc[2][3] += av.z * bv.w;                    \
        acc[3][0] += av.w * bv.x; acc[3][1] += av.w * bv.y;                    \
        acc[3][2] += av.w * bv.z; acc[3][3] += av.w * bv.w;                    \
    }

#define MT_STORE_A(dst, v0, v1)                                                \
    {                                                                          \
        dst[akq * 4 + 0][arow] = v0.x; dst[akq * 4 + 1][arow] = v0.y;          \
        dst[akq * 4 + 2][arow] = v0.z; dst[akq * 4 + 3][arow] = v0.w;          \
        dst[8 + akq * 4 + 0][arow] = v1.x; dst[8 + akq * 4 + 1][arow] = v1.y;  \
        dst[8 + akq * 4 + 2][arow] = v1.z; dst[8 + akq * 4 + 3][arow] = v1.w;  \
    }

// K2: E2 partial = E1 @ We2 over K-half z. grid (8,16,2), 128 thr.
__global__ void __launch_bounds__(128) k_gemmE2(const float* __restrict__ E1,
                                                const float* __restrict__ We2) {
    __shared__ float As[2][16][68];
    __shared__ float Bs[2][16][32];
    int tid = threadIdx.x;
    int tx = tid & 7, ty = tid >> 3;
    int arow = tid >> 1, akq = tid & 1;
    int brow = tid >> 3, bq = tid & 7;
    int row0 = blockIdx.y * 64, col0 = blockIdx.x * 32, kb = blockIdx.z * 128;
    const float* aptr = E1 + (row0 + arow) * 256 + kb + akq * 4;
    const float* bptr = We2 + (size_t)(kb + brow) * 256 + col0 + bq * 4;

    float4 a0 = *(const float4*)aptr;
    float4 a1 = *(const float4*)(aptr + 8);
    float4 b0 = *(const float4*)bptr;
    MT_STORE_A(As[0], a0, a1);
    *(float4*)&Bs[0][brow][bq * 4] = b0;
    __syncthreads();

    float acc[4][4] = {};
    int s = 0;
    for (int k0 = 0; k0 < 128; k0 += 16) {
        if (k0 + 16 < 128) {
            a0 = *(const float4*)(aptr + k0 + 16);
            a1 = *(const float4*)(aptr + k0 + 24);
            b0 = *(const float4*)(bptr + (size_t)(k0 + 16) * 256);
        }
        MT_COMPUTE(As[s], Bs[s])
        if (k0 + 16 < 128) {
            int ns = s ^ 1;
            MT_STORE_A(As[ns], a0, a1);
            *(float4*)&Bs[ns][brow][bq * 4] = b0;
            __syncthreads();
            s = ns;
        }
    }
    float* outp = g_E2 + (size_t)blockIdx.z * E2_HALF;
#pragma unroll
    for (int i = 0; i < 4; i++)
        *(float4*)(outp + (size_t)(row0 + ty * 4 + i) * 256 + col0 + tx * 4) =
            make_float4(acc[i][0], acc[i][1], acc[i][2], acc[i][3]);
}

// K3: NE partial = adj[:,kb:+128] @ relu(E2a+E2b+be2). z=b*2+ks. grid (8,4,8).
__global__ void __launch_bounds__(128) k_gemmNE(const float* __restrict__ adj,
                                                const float* __restrict__ be2) {
    __shared__ float As[2][16][68];
    __shared__ float Bs[2][16][32];
    int tid = threadIdx.x;
    int tx = tid & 7, ty = tid >> 3;
    int arow = tid >> 1, akq = tid & 1;
    int brow = tid >> 3, bq = tid & 7;
    int b = blockIdx.z >> 1, ks = blockIdx.z & 1, kb = ks * 128;
    int row0 = blockIdx.y * 64, col0 = blockIdx.x * 32;
    const float* aptr = adj + (row0 + arow) * 256 + kb + akq * 4;
    const float* pa = g_E2 + (size_t)(b * 256 + kb + brow) * 256 + col0 + bq * 4;
    const float* pb = pa + E2_HALF;
    float4 bi = *(const float4*)(be2 + col0 + bq * 4);

    float4 a0 = *(const float4*)aptr;
    float4 a1 = *(const float4*)(aptr + 8);
    float4 e0 = *(const float4*)pa;
    float4 f0 = *(const float4*)pb;
    MT_STORE_A(As[0], a0, a1);
    *(float4*)&Bs[0][brow][bq * 4] =
        make_float4(fmaxf(e0.x + f0.x + bi.x, 0.f), fmaxf(e0.y + f0.y + bi.y, 0.f),
                    fmaxf(e0.z + f0.z + bi.z, 0.f), fmaxf(e0.w + f0.w + bi.w, 0.f));
    __syncthreads();

    float acc[4][4] = {};
    int s = 0;
    for (int k0 = 0; k0 < 128; k0 += 16) {
        if (k0 + 16 < 128) {
            a0 = *(const float4*)(aptr + k0 + 16);
            a1 = *(const float4*)(aptr + k0 + 24);
            e0 = *(const float4*)(pa + (size_t)(k0 + 16) * 256);
            f0 = *(const float4*)(pb + (size_t)(k0 + 16) * 256);
        }
        MT_COMPUTE(As[s], Bs[s])
        if (k0 + 16 < 128) {
            int ns = s ^ 1;
            MT_STORE_A(As[ns], a0, a1);
            *(float4*)&Bs[ns][brow][bq * 4] =
                make_float4(fmaxf(e0.x + f0.x + bi.x, 0.f), fmaxf(e0.y + f0.y + bi.y, 0.f),
                            fmaxf(e0.z + f0.z + bi.z, 0.f), fmaxf(e0.w + f0.w + bi.w, 0.f));
            __syncthreads();
            s = ns;
        }
    }
    float* outp = g_NE + (size_t)ks * E2_HALF + (size_t)(b * 256) * 256;
#pragma unroll
    for (int i = 0; i < 4; i++)
        *(float4*)(outp + (size_t)(row0 + ty * 4 + i) * 256 + col0 + tx * 4) =
            make_float4(acc[i][0], acc[i][1], acc[i][2], acc[i][3]);
}

// K4: column sums of relu((NEa+NEb)@W + bias); z: 0->Wn/Sn, 1->Wh/Sh. grid (8,16,2).
__global__ void __launch_bounds__(128) k_colsum(const float* __restrict__ Wn,
                                                const float* __restrict__ bn,
                                                const float* __restrict__ Wh,
                                                const float* __restrict__ bh) {
    __shared__ float As[2][16][68];
    __shared__ float Bs[2][16][32];
    __shared__ float red[32];
    const float* W = blockIdx.z ? Wh : Wn;
    const float* bias = blockIdx.z ? bh : bn;
    float* S = blockIdx.z ? g_Sh : g_Sn;
    int tid = threadIdx.x;
    int tx = tid & 7, ty = tid >> 3;
    int arow = tid >> 1, akq = tid & 1;
    int brow = tid >> 3, bq = tid & 7;
    int row0 = blockIdx.y * 64, col0 = blockIdx.x * 32;
    int batch = blockIdx.y >> 2;
    const float* pa = g_NE + (size_t)(row0 + arow) * 256 + akq * 4;
    const float* pb = pa + E2_HALF;
    const float* bptr = W + (size_t)brow * 256 + col0 + bq * 4;

    float4 u0 = *(const float4*)pa, v0 = *(const float4*)pb;
    float4 u1 = *(const float4*)(pa + 8), v1 = *(const float4*)(pb + 8);
    float4 b0 = *(const float4*)bptr;
    float4 s0 = make_float4(u0.x + v0.x, u0.y + v0.y, u0.z + v0.z, u0.w + v0.w);
    float4 s1 = make_float4(u1.x + v1.x, u1.y + v1.y, u1.z + v1.z, u1.w + v1.w);
    MT_STORE_A(As[0], s0, s1);
    *(float4*)&Bs[0][brow][bq * 4] = b0;
    __syncthreads();

    float acc[4][4] = {};
    int s = 0;
    for (int k0 = 0; k0 < 256; k0 += 16) {
        if (k0 + 16 < 256) {
            u0 = *(const float4*)(pa + k0 + 16);
            v0 = *(const float4*)(pb + k0 + 16);
            u1 = *(const float4*)(pa + k0 + 24);
            v1 = *(const float4*)(pb + k0 + 24);
            b0 = *(const float4*)(bptr + (size_t)(k0 + 16) * 256);
        }
        MT_COMPUTE(As[s], Bs[s])
        if (k0 + 16 < 256) {
            int ns = s ^ 1;
            s0 = make_float4(u0.x + v0.x, u0.y + v0.y, u0.z + v0.z, u0.w + v0.w);
            s1 = make_float4(u1.x + v1.x, u1.y + v1.y, u1.z + v1.z, u1.w + v1.w);
            MT_STORE_A(As[ns], s0, s1);
            *(float4*)&Bs[ns][brow][bq * 4] = b0;
            __syncthreads();
            s = ns;
        }
    }
    if (tid < 32) red[tid] = 0.f;
    __syncthreads();
    float4 bi = *(const float4*)(bias + col0 + tx * 4);
    float ba4[4] = {bi.x, bi.y, bi.z, bi.w};
#pragma unroll
    for (int j = 0; j < 4; j++) {
        float sv = fmaxf(acc[0][j] + ba4[j], 0.f) + fmaxf(acc[1][j] + ba4[j], 0.f) +
                   fmaxf(acc[2][j] + ba4[j], 0.f) + fmaxf(acc[3][j] + ba4[j], 0.f);
        // reduce over the 4 ty-subgroups within the warp (lane bits 3,4)
        sv += __shfl_xor_sync(0xffffffffu, sv, 8);
        sv += __shfl_xor_sync(0xffffffffu, sv, 16);
        if ((tid & 31) < 8) atomicAdd(&red[tx * 4 + j], sv);
    }
    __syncthreads();
    if (tid < 32) atomicAdd(&S[batch * 256 + col0 + tid], red[tid]);
}

// ---------------------------------------------------------------------------
// ah split-K partials: grid 16 (4 batches x 4 k-segments of 64).
// vs = relu(E2a+E2b+be2) at row tgt; accumulates into g_AH.
__global__ void k_ah(const float* __restrict__ x, const float* __restrict__ Wl,
                     const float* __restrict__ be2) {
    __shared__ float vs[64];
    int b = blockIdx.x >> 2, kseg = blockIdx.x & 3;
    int t = threadIdx.x;
    int tgt = (int)x[b * 257 * 40 + 256 * 40];
    if (t < 64) {
        int col = kseg * 64 + t;
        size_t idx = (size_t)(b * 256 + tgt) * 256 + col;
        vs[t] = fmaxf(g_E2[idx] + g_E2[E2_HALF + idx] + be2[col], 0.f);
    }
    __syncthreads();
    float acc = 0.f;
#pragma unroll 8
    for (int k = 0; k < 64; k++)
        acc += vs[k] * Wl[(kseg * 64 + k) * 256 + t];
    atomicAdd(&g_AH[b * 256 + t], acc);
}

// ---------------------------------------------------------------------------
// logits = relu(AH+bl)*Sn; per-head softmax over DIM; head-mean of softmax*Sh;
// 32x8 output GEMM.
__global__ void k_final(const float* __restrict__ bl, const float* __restrict__ Wa,
                        const float* __restrict__ ba, float* __restrict__ out) {
    __shared__ float od[32];
    int b = blockIdx.x, tid = threadIdx.x;
    int h = tid >> 5, d = tid & 31;
    int t = d * 8 + h;                       // (DIM,HEAD) reshape index
    float ahv = fmaxf(g_AH[b * 256 + t] + bl[t], 0.f);
    float logit = ahv * g_Sn[b * 256 + t];
    float m = logit;
#pragma unroll
    for (int o = 16; o > 0; o >>= 1) m = fmaxf(m, __shfl_xor_sync(0xffffffffu, m, o));
    float e = expf(logit - m);
    float ssum = e;
#pragma unroll
    for (int o = 16; o > 0; o >>= 1) ssum += __shfl_xor_sync(0xffffffffu, ssum, o);
    float val = (e / ssum) * g_Sh[b * 256 + t] * 0.125f;
    if (tid < 32) od[tid] = 0.f;
    __syncthreads();
    atomicAdd(&od[d], val);
    __syncthreads();
    if (tid < 8) {
        float acc = ba[tid];
#pragma unroll
        for (int dd = 0; dd < 32; dd++) acc += od[dd] * Wa[dd * 8 + tid];
        out[b * 8 + tid] = acc;
    }
    (void)h;
}

// ---------------------------------------------------------------------------
extern "C" void kernel_launch(void* const* d_in, const int* in_sizes, int n_in,
                              void* d_out, int out_size) {
    const float* x   = (const float*)d_in[0];
    const float* adj = (const float*)d_in[1];
    const float* We1 = (const float*)d_in[2];
    const float* be1 = (const float*)d_in[3];
    const float* We2 = (const float*)d_in[4];
    const float* be2 = (const float*)d_in[5];
    const float* Wl  = (const float*)d_in[6];
    const float* bl  = (const float*)d_in[7];
    const float* Wn  = (const float*)d_in[8];
    const float* bn  = (const float*)d_in[9];
    const float* Wh  = (const float*)d_in[10];
    const float* bh  = (const float*)d_in[11];
    const float* Wa  = (const float*)d_in[12];
    const float* ba  = (const float*)d_in[13];
    float* out = (float*)d_out;

    float* pE1;
    cudaGetSymbolAddress((void**)&pE1, g_E1);

    k_embed1<<<256, 256>>>(x, We1, be1);
    k_gemmE2<<<dim3(8, 16, 2), 128>>>(pE1, We2);       // E2 partials (split-K)
    k_gemmNE<<<dim3(8, 4, 8), 128>>>(adj, be2);        // NE partials (split-K, fused relu)
    k_colsum<<<dim3(8, 16, 2), 128>>>(Wn, bn, Wh, bh); // S_n, S_h
    k_ah<<<16, 256>>>(x, Wl, be2);
    k_final<<<4, 256>>>(bl, Wa, ba, out);

    (void)in_sizes; (void)n_in; (void)out_size;
}